// round 16
// baseline (speedup 1.0000x reference)
#include <cuda_runtime.h>
#include <cstdint>

#define TWO_PI_F 6.28318530717958647692f

namespace {

constexpr int B = 4, S = 4096, V = 64, D = 128;

struct __align__(16) PosSmem {
    float xs2[2][V][2];    // [pair][j][half]  pair p = batches (2p, 2p+1)
    float hs2[2][V][2];
    float ls2[2][D][2];
    float h1s2[2][D][2];
    float red[2][B][2];    // [sum/sumsq][batch][warp-in-position]
};

// ---- f32x2 packed helpers --------------------------------------------------
__device__ __forceinline__ unsigned long long dup2(float a) {
    unsigned long long r; unsigned int u = __float_as_uint(a);
    asm("mov.b64 %0, {%1, %1};" : "=l"(r) : "r"(u));
    return r;
}
__device__ __forceinline__ unsigned long long pk2(float a, float b) {
    unsigned long long r;
    asm("mov.b64 %0, {%1, %2};" : "=l"(r) : "r"(__float_as_uint(a)), "r"(__float_as_uint(b)));
    return r;
}
__device__ __forceinline__ float2 unpk(unsigned long long v) {
    unsigned int lo, hi;
    asm("mov.b64 {%0, %1}, %2;" : "=r"(lo), "=r"(hi) : "l"(v));
    return make_float2(__uint_as_float(lo), __uint_as_float(hi));
}
__device__ __forceinline__ void ffma2(unsigned long long& d, unsigned long long a,
                                      unsigned long long b) {
    asm("fma.rn.f32x2 %0, %1, %2, %0;" : "+l"(d) : "l"(a), "l"(b));
}
__device__ __forceinline__ unsigned long long addp(unsigned long long a,
                                                   unsigned long long b) {
    unsigned long long r;
    asm("add.rn.f32x2 %0, %1, %2;" : "=l"(r) : "l"(a), "l"(b));
    return r;
}

// cos(2*pi*s/p): q may be off-by-one; r is then off by exactly one period,
// invisible to cos. |2*pi*r*rcp| <= ~4*pi, fine for MUFU.
__device__ __forceinline__ float phase_cos(float sf, float pf, float rcp) {
    float q = floorf(sf * rcp);
    float r = fmaf(-q, pf, sf);
    return __cosf(TWO_PI_F * (r * rcp));
}

// per-position barrier: syncs only the 64 threads (2 warps) of position ph.
// bar.sync has __syncthreads memory semantics (drains pending STS).
__device__ __forceinline__ void pos_bar(int ph) {
    asm volatile("bar.sync %0, 64;" :: "r"(ph + 1) : "memory");
}

} // namespace

// ---- packed weight scratch (position-invariant, rebuilt each launch) -------
__device__ float2 g_pk0[V * V];     // [j][i]: (charPT, 1/(i*V+j+2))
__device__ float2 g_pk1[D * D];     // [j][i]: (P1T, 1/(i*D+j+2))
__device__ float2 g_pk2[D * D];     // [j][i]: (P2T, 1/(i*D+j+2))
__device__ float2 g_mr [V * D];     // [j][i]: (M1T, R1T)
__device__ float  g_M2T[D * D];     // [j][i]

extern "C" __global__ void __launch_bounds__(256)
prep_weights(const float* __restrict__ charP, const float* __restrict__ M1,
             const float* __restrict__ R1,    const float* __restrict__ P1,
             const float* __restrict__ P2,    const float* __restrict__ M2)
{
    int t = blockIdx.x * blockDim.x + threadIdx.x;
    if (t < 4096) {                                   // charP 64x64
        int j = t >> 6, i = t & 63;
        g_pk0[t] = make_float2(charP[i * V + j], 1.0f / (float)(i * V + j + 2));
    } else if (t < 20480) {                           // P1 128x128
        int u = t - 4096; int j = u >> 7, i = u & 127;
        g_pk1[u] = make_float2(P1[i * D + j], 1.0f / (float)(i * D + j + 2));
    } else if (t < 36864) {                           // P2 128x128
        int u = t - 20480; int j = u >> 7, i = u & 127;
        g_pk2[u] = make_float2(P2[i * D + j], 1.0f / (float)(i * D + j + 2));
    } else if (t < 45056) {                           // M1,R1 64x128
        int u = t - 36864; int j = u >> 7, i = u & 127;
        g_mr[u] = make_float2(M1[i * V + j], R1[i * V + j]);
    } else if (t < 61440) {                           // M2 128x128
        int u = t - 45056; int j = u >> 7, i = u & 127;
        g_M2T[u] = M2[i * D + j];
    }
}

extern "C" __global__ void __launch_bounds__(128)
hier_kernel(const int* __restrict__ tokens, const int* __restrict__ positions,
            const float* __restrict__ emb,
            const float* __restrict__ g1, const float* __restrict__ b1v,
            const float* __restrict__ g2, const float* __restrict__ b2v,
            float* __restrict__ out)
{
    __shared__ PosSmem sm[2];

    const int tid  = (int)threadIdx.x;
    const int ph   = tid >> 6;            // position within CTA (0/1)
    const int t    = tid & 63;            // thread within position
    const int lane = tid & 31;
    const int wp   = (tid >> 5) & 1;      // warp within position
    const int sidx = blockIdx.x * 2 + ph;
    const float sf = (float)positions[sidx];
    PosSmem& PS = sm[ph];

    // ---- gather char embeddings ------------------------------------------
    {
        #pragma unroll
        for (int b = 0; b < B; ++b) {
            int tk = tokens[b * S + sidx];
            PS.xs2[b >> 1][t][b & 1] = emb[tk * V + t];
        }
    }
    pos_bar(ph);

    // ---- layer 0: h = (char_P .* phi64) @ x ------------------------------
    // thread t owns row i=t for BOTH pairs (phase computed once per (i,j)).
    {
        const int i = t;
        const float pbase = (float)(i * V + 2);
        unsigned long long acc0 = 0, acc1 = 0;
        #pragma unroll 8
        for (int j2 = 0; j2 < V / 2; ++j2) {
            ulonglong2 x0 = *reinterpret_cast<const ulonglong2*>(&PS.xs2[0][2 * j2][0]);
            ulonglong2 x1 = *reinterpret_cast<const ulonglong2*>(&PS.xs2[1][2 * j2][0]);
            #pragma unroll
            for (int e = 0; e < 2; ++e) {
                int j = 2 * j2 + e;
                float2 wr = g_pk0[j * V + i];
                float a = wr.x * phase_cos(sf, pbase + (float)j, wr.y);
                unsigned long long ad = dup2(a);
                ffma2(acc0, ad, e ? x0.y : x0.x);
                ffma2(acc1, ad, e ? x1.y : x1.x);
            }
        }
        *reinterpret_cast<unsigned long long*>(&PS.hs2[0][i][0]) = acc0;
        *reinterpret_cast<unsigned long long*>(&PS.hs2[1][i][0]) = acc1;
    }
    pos_bar(ph);

    const int i0 = t, i1 = t + 64;        // the two rows this thread owns

    // layernorm over 128 rows distributed 2/thread across 64 threads.
    auto layernorm2 = [&](float (&tv)[2][B], const float* gg, const float* bb,
                          float (&nv)[2][B]) {
        float s1[B], s2[B];
        #pragma unroll
        for (int b = 0; b < B; ++b) {
            s1[b] = tv[0][b] + tv[1][b];
            s2[b] = tv[0][b] * tv[0][b] + tv[1][b] * tv[1][b];
        }
        #pragma unroll
        for (int o = 16; o; o >>= 1) {
            #pragma unroll
            for (int b = 0; b < B; ++b) {
                s1[b] += __shfl_xor_sync(0xffffffffu, s1[b], o);
                s2[b] += __shfl_xor_sync(0xffffffffu, s2[b], o);
            }
        }
        if (lane == 0) {
            #pragma unroll
            for (int b = 0; b < B; ++b) {
                PS.red[0][b][wp] = s1[b];
                PS.red[1][b][wp] = s2[b];
            }
        }
        pos_bar(ph);
        const float gA = gg[i0], bA = bb[i0];
        const float gB = gg[i1], bB = bb[i1];
        #pragma unroll
        for (int b = 0; b < B; ++b) {
            float su = PS.red[0][b][0] + PS.red[0][b][1];
            float sq = PS.red[1][b][0] + PS.red[1][b][1];
            float mu  = su * (1.0f / D);
            float var = fmaf(sq, 1.0f / D, -mu * mu);
            float rs  = rsqrtf(var + 1e-5f);
            nv[0][b] = fmaf((tv[0][b] - mu) * rs, gA, bA);
            nv[1][b] = fmaf((tv[1][b] - mu) * rs, gB, bB);
        }
    };

    // ---- layer 1: t1 = M1 @ h and rv = R1 @ h (fused, 2 rows) ------------
    unsigned long long t1p[2][2] = {{0ull,0ull},{0ull,0ull}};
    unsigned long long rvp[2][2] = {{0ull,0ull},{0ull,0ull}};
    {
        #pragma unroll 8
        for (int j2 = 0; j2 < V / 2; ++j2) {
            ulonglong2 x0 = *reinterpret_cast<const ulonglong2*>(&PS.hs2[0][2 * j2][0]);
            ulonglong2 x1 = *reinterpret_cast<const ulonglong2*>(&PS.hs2[1][2 * j2][0]);
            #pragma unroll
            for (int e = 0; e < 2; ++e) {
                int j = 2 * j2 + e;
                float2 wA = g_mr[j * D + i0];
                float2 wB = g_mr[j * D + i1];
                unsigned long long xm0 = e ? x0.y : x0.x;
                unsigned long long xm1 = e ? x1.y : x1.x;
                unsigned long long mA = dup2(wA.x), rA = dup2(wA.y);
                unsigned long long mB = dup2(wB.x), rB = dup2(wB.y);
                ffma2(t1p[0][0], mA, xm0); ffma2(t1p[0][1], mA, xm1);
                ffma2(t1p[1][0], mB, xm0); ffma2(t1p[1][1], mB, xm1);
                ffma2(rvp[0][0], rA, xm0); ffma2(rvp[0][1], rA, xm1);
                ffma2(rvp[1][0], rB, xm0); ffma2(rvp[1][1], rB, xm1);
            }
        }
    }
    // layernorm(t1) -> ls2
    {
        float tv[2][B], nv[2][B];
        #pragma unroll
        for (int r = 0; r < 2; ++r) {
            float2 a0 = unpk(t1p[r][0]), a1 = unpk(t1p[r][1]);
            tv[r][0] = a0.x; tv[r][1] = a0.y; tv[r][2] = a1.x; tv[r][3] = a1.y;
        }
        layernorm2(tv, g1, b1v, nv);
        *reinterpret_cast<unsigned long long*>(&PS.ls2[0][i0][0]) = pk2(nv[0][0], nv[0][1]);
        *reinterpret_cast<unsigned long long*>(&PS.ls2[1][i0][0]) = pk2(nv[0][2], nv[0][3]);
        *reinterpret_cast<unsigned long long*>(&PS.ls2[0][i1][0]) = pk2(nv[1][0], nv[1][1]);
        *reinterpret_cast<unsigned long long*>(&PS.ls2[1][i1][0]) = pk2(nv[1][2], nv[1][3]);
    }
    pos_bar(ph);

    const float pb0 = (float)(i0 * D + 2);
    const float pb1 = (float)(i1 * D + 2);

    // ---- layer 1 pos_nk + residual ---------------------------------------
    unsigned long long h1p[2][2] = {{0ull,0ull},{0ull,0ull}};
    {
        #pragma unroll 4
        for (int j2 = 0; j2 < D / 2; ++j2) {
            ulonglong2 x0 = *reinterpret_cast<const ulonglong2*>(&PS.ls2[0][2 * j2][0]);
            ulonglong2 x1 = *reinterpret_cast<const ulonglong2*>(&PS.ls2[1][2 * j2][0]);
            #pragma unroll
            for (int e = 0; e < 2; ++e) {
                int j = 2 * j2 + e;
                float2 wA = g_pk1[j * D + i0];
                float2 wB = g_pk1[j * D + i1];
                float aA = wA.x * phase_cos(sf, pb0 + (float)j, wA.y);
                float aB = wB.x * phase_cos(sf, pb1 + (float)j, wB.y);
                unsigned long long adA = dup2(aA), adB = dup2(aB);
                unsigned long long xm0 = e ? x0.y : x0.x;
                unsigned long long xm1 = e ? x1.y : x1.x;
                ffma2(h1p[0][0], adA, xm0); ffma2(h1p[0][1], adA, xm1);
                ffma2(h1p[1][0], adB, xm0); ffma2(h1p[1][1], adB, xm1);
            }
        }
        #pragma unroll
        for (int r = 0; r < 2; ++r) {
            h1p[r][0] = addp(h1p[r][0], rvp[r][0]);
            h1p[r][1] = addp(h1p[r][1], rvp[r][1]);
        }
        *reinterpret_cast<unsigned long long*>(&PS.h1s2[0][i0][0]) = h1p[0][0];
        *reinterpret_cast<unsigned long long*>(&PS.h1s2[1][i0][0]) = h1p[0][1];
        *reinterpret_cast<unsigned long long*>(&PS.h1s2[0][i1][0]) = h1p[1][0];
        *reinterpret_cast<unsigned long long*>(&PS.h1s2[1][i1][0]) = h1p[1][1];
    }
    pos_bar(ph);

    // ---- layer 2: t2 = M2 @ h1 -------------------------------------------
    unsigned long long t2p[2][2] = {{0ull,0ull},{0ull,0ull}};
    {
        #pragma unroll 8
        for (int j2 = 0; j2 < D / 2; ++j2) {
            ulonglong2 x0 = *reinterpret_cast<const ulonglong2*>(&PS.h1s2[0][2 * j2][0]);
            ulonglong2 x1 = *reinterpret_cast<const ulonglong2*>(&PS.h1s2[1][2 * j2][0]);
            #pragma unroll
            for (int e = 0; e < 2; ++e) {
                int j = 2 * j2 + e;
                unsigned long long mA = dup2(g_M2T[j * D + i0]);
                unsigned long long mB = dup2(g_M2T[j * D + i1]);
                unsigned long long xm0 = e ? x0.y : x0.x;
                unsigned long long xm1 = e ? x1.y : x1.x;
                ffma2(t2p[0][0], mA, xm0); ffma2(t2p[0][1], mA, xm1);
                ffma2(t2p[1][0], mB, xm0); ffma2(t2p[1][1], mB, xm1);
            }
        }
    }
    // layernorm(t2) -> ls2 (safe: last ls2 readers finished before h1 bar)
    {
        float tv[2][B], nv[2][B];
        #pragma unroll
        for (int r = 0; r < 2; ++r) {
            float2 a0 = unpk(t2p[r][0]), a1 = unpk(t2p[r][1]);
            tv[r][0] = a0.x; tv[r][1] = a0.y; tv[r][2] = a1.x; tv[r][3] = a1.y;
        }
        layernorm2(tv, g2, b2v, nv);
        pos_bar(ph);
        *reinterpret_cast<unsigned long long*>(&PS.ls2[0][i0][0]) = pk2(nv[0][0], nv[0][1]);
        *reinterpret_cast<unsigned long long*>(&PS.ls2[1][i0][0]) = pk2(nv[0][2], nv[0][3]);
        *reinterpret_cast<unsigned long long*>(&PS.ls2[0][i1][0]) = pk2(nv[1][0], nv[1][1]);
        *reinterpret_cast<unsigned long long*>(&PS.ls2[1][i1][0]) = pk2(nv[1][2], nv[1][3]);
    }
    pos_bar(ph);

    // ---- layer 2 pos_nk + shared residual t2 ------------------------------
    unsigned long long ovp[2][2] = {{0ull,0ull},{0ull,0ull}};
    {
        #pragma unroll 4
        for (int j2 = 0; j2 < D / 2; ++j2) {
            ulonglong2 x0 = *reinterpret_cast<const ulonglong2*>(&PS.ls2[0][2 * j2][0]);
            ulonglong2 x1 = *reinterpret_cast<const ulonglong2*>(&PS.ls2[1][2 * j2][0]);
            #pragma unroll
            for (int e = 0; e < 2; ++e) {
                int j = 2 * j2 + e;
                float2 wA = g_pk2[j * D + i0];
                float2 wB = g_pk2[j * D + i1];
                float aA = wA.x * phase_cos(sf, pb0 + (float)j, wA.y);
                float aB = wB.x * phase_cos(sf, pb1 + (float)j, wB.y);
                unsigned long long adA = dup2(aA), adB = dup2(aB);
                unsigned long long xm0 = e ? x0.y : x0.x;
                unsigned long long xm1 = e ? x1.y : x1.x;
                ffma2(ovp[0][0], adA, xm0); ffma2(ovp[0][1], adA, xm1);
                ffma2(ovp[1][0], adB, xm0); ffma2(ovp[1][1], adB, xm1);
            }
        }
    }
    {
        float2 o00 = unpk(addp(ovp[0][0], t2p[0][0]));   // row i0, batches 0/1
        float2 o01 = unpk(addp(ovp[0][1], t2p[0][1]));   // row i0, batches 2/3
        float2 o10 = unpk(addp(ovp[1][0], t2p[1][0]));   // row i1, batches 0/1
        float2 o11 = unpk(addp(ovp[1][1], t2p[1][1]));   // row i1, batches 2/3
        out[(0 * S + sidx) * D + i0] = o00.x;
        out[(1 * S + sidx) * D + i0] = o00.y;
        out[(2 * S + sidx) * D + i0] = o01.x;
        out[(3 * S + sidx) * D + i0] = o01.y;
        out[(0 * S + sidx) * D + i1] = o10.x;
        out[(1 * S + sidx) * D + i1] = o10.y;
        out[(2 * S + sidx) * D + i1] = o11.x;
        out[(3 * S + sidx) * D + i1] = o11.y;
    }
}

extern "C" void kernel_launch(void* const* d_in, const int* in_sizes, int n_in,
                              void* d_out, int out_size) {
    const int*   tokens    = (const int*)d_in[0];
    const int*   positions = (const int*)d_in[1];
    const float* emb       = (const float*)d_in[2];
    const float* charP     = (const float*)d_in[3];
    const float* M1        = (const float*)d_in[4];
    const float* P1        = (const float*)d_in[5];
    const float* g1        = (const float*)d_in[6];
    const float* b1        = (const float*)d_in[7];
    const float* R1        = (const float*)d_in[8];
    const float* M2        = (const float*)d_in[9];
    const float* P2        = (const float*)d_in[10];
    const float* g2        = (const float*)d_in[11];
    const float* b2        = (const float*)d_in[12];
    float* out = (float*)d_out;

    prep_weights<<<(61440 + 255) / 256, 256>>>(charP, M1, R1, P1, P2, M2);

    hier_kernel<<<S / 2, 128>>>(tokens, positions, emb, g1, b1, g2, b2, out);
}

// round 17
// speedup vs baseline: 1.3790x; 1.3790x over previous
#include <cuda_runtime.h>
#include <cstdint>

#define TWO_PI_F 6.28318530717958647692f

namespace {

constexpr int B = 4, S = 4096, V = 64, D = 128;

struct __align__(16) PosSmem {
    float xs2[2][V][2];    // [pair][j][half]  pair p = batches (2p, 2p+1)
    float hs2[2][V][2];
    float ls2[2][D][2];
    float h1s2[2][D][2];
    float red[2][B][2];    // [sum/sumsq][batch][warp-in-position]
};

// ---- f32x2 packed helpers --------------------------------------------------
__device__ __forceinline__ unsigned long long dup2(float a) {
    unsigned long long r; unsigned int u = __float_as_uint(a);
    asm("mov.b64 %0, {%1, %1};" : "=l"(r) : "r"(u));
    return r;
}
__device__ __forceinline__ unsigned long long pk2(float a, float b) {
    unsigned long long r;
    asm("mov.b64 %0, {%1, %2};" : "=l"(r) : "r"(__float_as_uint(a)), "r"(__float_as_uint(b)));
    return r;
}
__device__ __forceinline__ float2 unpk(unsigned long long v) {
    unsigned int lo, hi;
    asm("mov.b64 {%0, %1}, %2;" : "=r"(lo), "=r"(hi) : "l"(v));
    return make_float2(__uint_as_float(lo), __uint_as_float(hi));
}
__device__ __forceinline__ void ffma2(unsigned long long& d, unsigned long long a,
                                      unsigned long long b) {
    asm("fma.rn.f32x2 %0, %1, %2, %0;" : "+l"(d) : "l"(a), "l"(b));
}
__device__ __forceinline__ unsigned long long addp(unsigned long long a,
                                                   unsigned long long b) {
    unsigned long long r;
    asm("add.rn.f32x2 %0, %1, %2;" : "=l"(r) : "l"(a), "l"(b));
    return r;
}

// cos(2*pi*s/p): q may be off-by-one; r is then off by exactly one period,
// invisible to cos. |2*pi*r*rcp| <= ~4*pi, fine for MUFU.
__device__ __forceinline__ float phase_cos(float sf, float pf, float rcp) {
    float q = floorf(sf * rcp);
    float r = fmaf(-q, pf, sf);
    return __cosf(TWO_PI_F * (r * rcp));
}

} // namespace

// ---- packed weight scratch (position-invariant, rebuilt each launch) -------
__device__ float2 g_pk0[V * V];     // [j][i]: (charPT, 1/(i*V+j+2))
__device__ float2 g_pk1[D * D];     // [j][i]: (P1T, 1/(i*D+j+2))
__device__ float2 g_pk2[D * D];     // [j][i]: (P2T, 1/(i*D+j+2))
__device__ float2 g_mr [V * D];     // [j][i]: (M1T, R1T)
__device__ float  g_M2T[D * D];     // [j][i]

extern "C" __global__ void __launch_bounds__(256)
prep_weights(const float* __restrict__ charP, const float* __restrict__ M1,
             const float* __restrict__ R1,    const float* __restrict__ P1,
             const float* __restrict__ P2,    const float* __restrict__ M2)
{
    int t = blockIdx.x * blockDim.x + threadIdx.x;
    if (t < 4096) {                                   // charP 64x64
        int j = t >> 6, i = t & 63;
        g_pk0[t] = make_float2(charP[i * V + j], 1.0f / (float)(i * V + j + 2));
    } else if (t < 20480) {                           // P1 128x128
        int u = t - 4096; int j = u >> 7, i = u & 127;
        g_pk1[u] = make_float2(P1[i * D + j], 1.0f / (float)(i * D + j + 2));
    } else if (t < 36864) {                           // P2 128x128
        int u = t - 20480; int j = u >> 7, i = u & 127;
        g_pk2[u] = make_float2(P2[i * D + j], 1.0f / (float)(i * D + j + 2));
    } else if (t < 45056) {                           // M1,R1 64x128
        int u = t - 36864; int j = u >> 7, i = u & 127;
        g_mr[u] = make_float2(M1[i * V + j], R1[i * V + j]);
    } else if (t < 61440) {                           // M2 128x128
        int u = t - 45056; int j = u >> 7, i = u & 127;
        g_M2T[u] = M2[i * D + j];
    }
}

extern "C" __global__ void __launch_bounds__(128)
hier_kernel(const int* __restrict__ tokens, const int* __restrict__ positions,
            const float* __restrict__ emb,
            const float* __restrict__ g1, const float* __restrict__ b1v,
            const float* __restrict__ g2, const float* __restrict__ b2v,
            float* __restrict__ out)
{
    __shared__ PosSmem sm[2];

    const int tid  = (int)threadIdx.x;
    const int ph   = tid >> 6;            // position within CTA (0/1)
    const int t    = tid & 63;            // thread within position
    const int lane = tid & 31;
    const int wp   = (tid >> 5) & 1;      // warp within position
    const int sidx = blockIdx.x * 2 + ph;
    const float sf = (float)positions[sidx];
    PosSmem& PS = sm[ph];

    // ---- gather char embeddings ------------------------------------------
    {
        #pragma unroll
        for (int b = 0; b < B; ++b) {
            int tk = tokens[b * S + sidx];
            PS.xs2[b >> 1][t][b & 1] = emb[tk * V + t];
        }
    }
    __syncthreads();

    // ---- layer 0: h = (char_P .* phi64) @ x ------------------------------
    // thread t owns row i=t for BOTH pairs (phase computed once per (i,j)).
    {
        const int i = t;
        const float pbase = (float)(i * V + 2);
        unsigned long long acc0 = 0, acc1 = 0;
        #pragma unroll 8
        for (int j2 = 0; j2 < V / 2; ++j2) {
            ulonglong2 x0 = *reinterpret_cast<const ulonglong2*>(&PS.xs2[0][2 * j2][0]);
            ulonglong2 x1 = *reinterpret_cast<const ulonglong2*>(&PS.xs2[1][2 * j2][0]);
            #pragma unroll
            for (int e = 0; e < 2; ++e) {
                int j = 2 * j2 + e;
                float2 wr = g_pk0[j * V + i];
                float a = wr.x * phase_cos(sf, pbase + (float)j, wr.y);
                unsigned long long ad = dup2(a);
                ffma2(acc0, ad, e ? x0.y : x0.x);
                ffma2(acc1, ad, e ? x1.y : x1.x);
            }
        }
        *reinterpret_cast<unsigned long long*>(&PS.hs2[0][i][0]) = acc0;
        *reinterpret_cast<unsigned long long*>(&PS.hs2[1][i][0]) = acc1;
    }
    __syncthreads();

    const int i0 = t, i1 = t + 64;        // the two rows this thread owns

    // layernorm over 128 rows distributed 2/thread across 64 threads.
    auto layernorm2 = [&](float (&tv)[2][B], const float* gg, const float* bb,
                          float (&nv)[2][B]) {
        float s1[B], s2[B];
        #pragma unroll
        for (int b = 0; b < B; ++b) {
            s1[b] = tv[0][b] + tv[1][b];
            s2[b] = tv[0][b] * tv[0][b] + tv[1][b] * tv[1][b];
        }
        #pragma unroll
        for (int o = 16; o; o >>= 1) {
            #pragma unroll
            for (int b = 0; b < B; ++b) {
                s1[b] += __shfl_xor_sync(0xffffffffu, s1[b], o);
                s2[b] += __shfl_xor_sync(0xffffffffu, s2[b], o);
            }
        }
        if (lane == 0) {
            #pragma unroll
            for (int b = 0; b < B; ++b) {
                PS.red[0][b][wp] = s1[b];
                PS.red[1][b][wp] = s2[b];
            }
        }
        __syncthreads();
        const float gA = gg[i0], bA = bb[i0];
        const float gB = gg[i1], bB = bb[i1];
        #pragma unroll
        for (int b = 0; b < B; ++b) {
            float su = PS.red[0][b][0] + PS.red[0][b][1];
            float sq = PS.red[1][b][0] + PS.red[1][b][1];
            float mu  = su * (1.0f / D);
            float var = fmaf(sq, 1.0f / D, -mu * mu);
            float rs  = rsqrtf(var + 1e-5f);
            nv[0][b] = fmaf((tv[0][b] - mu) * rs, gA, bA);
            nv[1][b] = fmaf((tv[1][b] - mu) * rs, gB, bB);
        }
    };

    // ---- layer 1: t1 = M1 @ h and rv = R1 @ h (fused, 2 rows) ------------
    unsigned long long t1p[2][2] = {{0ull,0ull},{0ull,0ull}};
    unsigned long long rvp[2][2] = {{0ull,0ull},{0ull,0ull}};
    {
        #pragma unroll 8
        for (int j2 = 0; j2 < V / 2; ++j2) {
            ulonglong2 x0 = *reinterpret_cast<const ulonglong2*>(&PS.hs2[0][2 * j2][0]);
            ulonglong2 x1 = *reinterpret_cast<const ulonglong2*>(&PS.hs2[1][2 * j2][0]);
            #pragma unroll
            for (int e = 0; e < 2; ++e) {
                int j = 2 * j2 + e;
                float2 wA = g_mr[j * D + i0];
                float2 wB = g_mr[j * D + i1];
                unsigned long long xm0 = e ? x0.y : x0.x;
                unsigned long long xm1 = e ? x1.y : x1.x;
                unsigned long long mA = dup2(wA.x), rA = dup2(wA.y);
                unsigned long long mB = dup2(wB.x), rB = dup2(wB.y);
                ffma2(t1p[0][0], mA, xm0); ffma2(t1p[0][1], mA, xm1);
                ffma2(t1p[1][0], mB, xm0); ffma2(t1p[1][1], mB, xm1);
                ffma2(rvp[0][0], rA, xm0); ffma2(rvp[0][1], rA, xm1);
                ffma2(rvp[1][0], rB, xm0); ffma2(rvp[1][1], rB, xm1);
            }
        }
    }
    // layernorm(t1) -> ls2
    {
        float tv[2][B], nv[2][B];
        #pragma unroll
        for (int r = 0; r < 2; ++r) {
            float2 a0 = unpk(t1p[r][0]), a1 = unpk(t1p[r][1]);
            tv[r][0] = a0.x; tv[r][1] = a0.y; tv[r][2] = a1.x; tv[r][3] = a1.y;
        }
        layernorm2(tv, g1, b1v, nv);
        *reinterpret_cast<unsigned long long*>(&PS.ls2[0][i0][0]) = pk2(nv[0][0], nv[0][1]);
        *reinterpret_cast<unsigned long long*>(&PS.ls2[1][i0][0]) = pk2(nv[0][2], nv[0][3]);
        *reinterpret_cast<unsigned long long*>(&PS.ls2[0][i1][0]) = pk2(nv[1][0], nv[1][1]);
        *reinterpret_cast<unsigned long long*>(&PS.ls2[1][i1][0]) = pk2(nv[1][2], nv[1][3]);
    }
    __syncthreads();

    const float pb0 = (float)(i0 * D + 2);
    const float pb1 = (float)(i1 * D + 2);

    // ---- layer 1 pos_nk + residual ---------------------------------------
    unsigned long long h1p[2][2] = {{0ull,0ull},{0ull,0ull}};
    {
        #pragma unroll 4
        for (int j2 = 0; j2 < D / 2; ++j2) {
            ulonglong2 x0 = *reinterpret_cast<const ulonglong2*>(&PS.ls2[0][2 * j2][0]);
            ulonglong2 x1 = *reinterpret_cast<const ulonglong2*>(&PS.ls2[1][2 * j2][0]);
            #pragma unroll
            for (int e = 0; e < 2; ++e) {
                int j = 2 * j2 + e;
                float2 wA = g_pk1[j * D + i0];
                float2 wB = g_pk1[j * D + i1];
                float aA = wA.x * phase_cos(sf, pb0 + (float)j, wA.y);
                float aB = wB.x * phase_cos(sf, pb1 + (float)j, wB.y);
                unsigned long long adA = dup2(aA), adB = dup2(aB);
                unsigned long long xm0 = e ? x0.y : x0.x;
                unsigned long long xm1 = e ? x1.y : x1.x;
                ffma2(h1p[0][0], adA, xm0); ffma2(h1p[0][1], adA, xm1);
                ffma2(h1p[1][0], adB, xm0); ffma2(h1p[1][1], adB, xm1);
            }
        }
        #pragma unroll
        for (int r = 0; r < 2; ++r) {
            h1p[r][0] = addp(h1p[r][0], rvp[r][0]);
            h1p[r][1] = addp(h1p[r][1], rvp[r][1]);
        }
        *reinterpret_cast<unsigned long long*>(&PS.h1s2[0][i0][0]) = h1p[0][0];
        *reinterpret_cast<unsigned long long*>(&PS.h1s2[1][i0][0]) = h1p[0][1];
        *reinterpret_cast<unsigned long long*>(&PS.h1s2[0][i1][0]) = h1p[1][0];
        *reinterpret_cast<unsigned long long*>(&PS.h1s2[1][i1][0]) = h1p[1][1];
    }
    __syncthreads();

    // ---- layer 2: t2 = M2 @ h1 -------------------------------------------
    unsigned long long t2p[2][2] = {{0ull,0ull},{0ull,0ull}};
    {
        #pragma unroll 8
        for (int j2 = 0; j2 < D / 2; ++j2) {
            ulonglong2 x0 = *reinterpret_cast<const ulonglong2*>(&PS.h1s2[0][2 * j2][0]);
            ulonglong2 x1 = *reinterpret_cast<const ulonglong2*>(&PS.h1s2[1][2 * j2][0]);
            #pragma unroll
            for (int e = 0; e < 2; ++e) {
                int j = 2 * j2 + e;
                unsigned long long mA = dup2(g_M2T[j * D + i0]);
                unsigned long long mB = dup2(g_M2T[j * D + i1]);
                unsigned long long xm0 = e ? x0.y : x0.x;
                unsigned long long xm1 = e ? x1.y : x1.x;
                ffma2(t2p[0][0], mA, xm0); ffma2(t2p[0][1], mA, xm1);
                ffma2(t2p[1][0], mB, xm0); ffma2(t2p[1][1], mB, xm1);
            }
        }
    }
    // layernorm(t2) -> ls2 (safe: last ls2 readers finished before h1 sync)
    {
        float tv[2][B], nv[2][B];
        #pragma unroll
        for (int r = 0; r < 2; ++r) {
            float2 a0 = unpk(t2p[r][0]), a1 = unpk(t2p[r][1]);
            tv[r][0] = a0.x; tv[r][1] = a0.y; tv[r][2] = a1.x; tv[r][3] = a1.y;
        }
        layernorm2(tv, g2, b2v, nv);
        __syncthreads();
        *reinterpret_cast<unsigned long long*>(&PS.ls2[0][i0][0]) = pk2(nv[0][0], nv[0][1]);
        *reinterpret_cast<unsigned long long*>(&PS.ls2[1][i0][0]) = pk2(nv[0][2], nv[0][3]);
        *reinterpret_cast<unsigned long long*>(&PS.ls2[0][i1][0]) = pk2(nv[1][0], nv[1][1]);
        *reinterpret_cast<unsigned long long*>(&PS.ls2[1][i1][0]) = pk2(nv[1][2], nv[1][3]);
    }
    __syncthreads();

    // ---- layer 2 pos_nk + shared residual t2 ------------------------------
    unsigned long long ovp[2][2] = {{0ull,0ull},{0ull,0ull}};
    {
        #pragma unroll 4
        for (int j2 = 0; j2 < D / 2; ++j2) {
            ulonglong2 x0 = *reinterpret_cast<const ulonglong2*>(&PS.ls2[0][2 * j2][0]);
            ulonglong2 x1 = *reinterpret_cast<const ulonglong2*>(&PS.ls2[1][2 * j2][0]);
            #pragma unroll
            for (int e = 0; e < 2; ++e) {
                int j = 2 * j2 + e;
                float2 wA = g_pk2[j * D + i0];
                float2 wB = g_pk2[j * D + i1];
                float aA = wA.x * phase_cos(sf, pb0 + (float)j, wA.y);
                float aB = wB.x * phase_cos(sf, pb1 + (float)j, wB.y);
                unsigned long long adA = dup2(aA), adB = dup2(aB);
                unsigned long long xm0 = e ? x0.y : x0.x;
                unsigned long long xm1 = e ? x1.y : x1.x;
                ffma2(ovp[0][0], adA, xm0); ffma2(ovp[0][1], adA, xm1);
                ffma2(ovp[1][0], adB, xm0); ffma2(ovp[1][1], adB, xm1);
            }
        }
    }
    {
        float2 o00 = unpk(addp(ovp[0][0], t2p[0][0]));   // row i0, batches 0/1
        float2 o01 = unpk(addp(ovp[0][1], t2p[0][1]));   // row i0, batches 2/3
        float2 o10 = unpk(addp(ovp[1][0], t2p[1][0]));   // row i1, batches 0/1
        float2 o11 = unpk(addp(ovp[1][1], t2p[1][1]));   // row i1, batches 2/3
        out[(0 * S + sidx) * D + i0] = o00.x;
        out[(1 * S + sidx) * D + i0] = o00.y;
        out[(2 * S + sidx) * D + i0] = o01.x;
        out[(3 * S + sidx) * D + i0] = o01.y;
        out[(0 * S + sidx) * D + i1] = o10.x;
        out[(1 * S + sidx) * D + i1] = o10.y;
        out[(2 * S + sidx) * D + i1] = o11.x;
        out[(3 * S + sidx) * D + i1] = o11.y;
    }
}

extern "C" void kernel_launch(void* const* d_in, const int* in_sizes, int n_in,
                              void* d_out, int out_size) {
    const int*   tokens    = (const int*)d_in[0];
    const int*   positions = (const int*)d_in[1];
    const float* emb       = (const float*)d_in[2];
    const float* charP     = (const float*)d_in[3];
    const float* M1        = (const float*)d_in[4];
    const float* P1        = (const float*)d_in[5];
    const float* g1        = (const float*)d_in[6];
    const float* b1        = (const float*)d_in[7];
    const float* R1        = (const float*)d_in[8];
    const float* M2        = (const float*)d_in[9];
    const float* P2        = (const float*)d_in[10];
    const float* g2        = (const float*)d_in[11];
    const float* b2        = (const float*)d_in[12];
    float* out = (float*)d_out;

    prep_weights<<<(61440 + 255) / 256, 256>>>(charP, M1, R1, P1, P2, M2);

    hier_kernel<<<S / 2, 128>>>(tokens, positions, emb, g1, b1, g2, b2, out);
}